// round 8
// baseline (speedup 1.0000x reference)
#include <cuda_runtime.h>

#define INN   40
#define HID   16384
#define OUTN  22
#define FAN0  8192
#define FAN1  11
#define THRESH 0.3f
#define NBLK  32
#define NTHR  512
#define NWARP (NTHR / 32)
#define NTOT  (NBLK * NTHR)             // 16384 threads == HID
#define DECAY 0.95122942450071400910f   // float32(exp(-1/20))

// Scratch — __device__ globals (allocation-free rule). g_add_h / g_add_o are
// zero at load and restored to zero every execution (zero-on-consume). g_bar is
// MONOTONIC (never reset): replay r uses window [2r*NBLK, 2(r+1)*NBLK); g_gen
// is the replay counter (bumped once per replay by bar1's last arriver).
__device__ float g_add_h[HID];
__device__ float g_add_o[OUTN];
__device__ __align__(128) unsigned g_bar[32];   // [0]: monotonic arrival counter
__device__ __align__(128) unsigned g_gen[32];   // [0]: replay index

__global__ __launch_bounds__(NTHR, 1)
void snn_fused(const float* __restrict__ spikes,
               const float* __restrict__ w0,
               const int*   __restrict__ tgt0,
               const float* __restrict__ w1,
               const int*   __restrict__ tgt1,
               const int*   __restrict__ mt_p,
               float*       __restrict__ out)
{
    __shared__ float s_spk[INN];          // 2 * input_spikes
    __shared__ float s_bins[NWARP][24];   // warp-private output bins (22 used)

    const int tid = threadIdx.x;
    const int gid = blockIdx.x * NTHR + tid;   // one hidden neuron per thread
    const int wrp = tid >> 5;
    const int lan = tid & 31;

    // ── Stage spikes (broadcast line) + zero bins
    if (tid < INN) s_spk[tid] = 2.0f * spikes[tid];
    if (lan < 24) s_bins[wrp][lan] = 0.0f;

    // ── Vectorized speculative prefetch of phase-B operands.
    // Flat element space [0, 40*8192). Thread owns float4 chunks at
    // vec index gid + 16384*k (k=0..4): 5 float4 + 5 int4 = 10 wide LDGs.
    // Chunk k lives entirely in row i = (gid>>11) + 8k (warp-uniform).
    const float4* w0v = (const float4*)w0;
    const int4*   t0v = (const int4*)tgt0;
    float4 wv[5];
    int4   tv[5];
#pragma unroll
    for (int k = 0; k < 5; ++k) {
        wv[k] = __ldg(w0v + (gid + NTOT * k));
        tv[k] = __ldg(t0v + (gid + NTOT * k));
    }

    // ── Prefetch phase-C operands (consumed after barrier 1)
    float w1r[FAN1];
    int   t1r[FAN1];
    {
        const float* wr = w1   + gid * FAN1;
        const int*   tr = tgt1 + gid * FAN1;
#pragma unroll
        for (int q = 0; q < FAN1; ++q) { w1r[q] = __ldg(wr + q); t1r[q] = __ldg(tr + q); }
    }
    const int mt = __ldg(mt_p);
    const unsigned gen = *(volatile unsigned*)&g_gen[0];   // replay index

    // fac_long = decay^(mt-1) (hidden under phase B; finisher/repair only)
    float fac_long = 1.0f;
    for (int k = 1; k < mt; ++k) fac_long *= DECAY;

    __syncthreads();   // s_spk + bins visible

    // ── Phase B: input -> hidden scatter (t=0). Per chunk: one warp-uniform
    // spike lookup, 4 predicated REDs with operands already in registers.
    const int i0 = gid >> 11;
#pragma unroll
    for (int k = 0; k < 5; ++k) {
        const float s = s_spk[i0 + 8 * k];
        if (s != 0.0f) {
            atomicAdd(&g_add_h[tv[k].x], s * wv[k].x);
            atomicAdd(&g_add_h[tv[k].y], s * wv[k].y);
            atomicAdd(&g_add_h[tv[k].z], s * wv[k].z);
            atomicAdd(&g_add_h[tv[k].w], s * wv[k].w);
        }
    }

    // ── Barrier 1: counter-direct. The last arrival IS the release; spinners
    // poll the counter itself (no separate gate-write hop).
    __syncthreads();
    if (tid == 0) {
        __threadfence();                                       // release
        const unsigned tgt = (2u * gen + 1u) * NBLK;
        unsigned old = atomicAdd(&g_bar[0], 1u);
        if (old == tgt - 1u) {
            *(volatile unsigned*)&g_gen[0] = gen + 1u;         // replay ctr (off-path)
        } else {
            while (*(volatile unsigned*)&g_bar[0] < tgt) { }
        }
        __threadfence();                                       // acquire
    }
    __syncthreads();

    // ── Phase C: hidden threshold (spikes possible only at t=0) + out scatter
    float a = g_add_h[gid] * DECAY;               // pot_h at end of t=0
    g_add_h[gid] = 0.0f;                          // zero-on-consume for replay
    const bool  sp  = (a >= THRESH);
    const float pot = sp ? 0.0f : a;

    // Speculative pot_h store: assume all_f=true => S=2 => fac=DECAY.
    out[2 * OUTN + gid] = (mt >= 1) ? pot * DECAY : 0.0f;

    if (sp) {
#pragma unroll
        for (int q = 0; q < FAN1; ++q)
            atomicAdd(&s_bins[wrp][t1r[q]], w1r[q]);   // prefetched, no loads
    }
    __syncthreads();
    if (wrp != 0) return;                          // warps 1..15 done

    // ── Warp 0: post output partials, arrive; only the LAST block finalizes.
    float v = 0.0f;
    if (lan < OUTN) {
#pragma unroll
        for (int w = 0; w < NWARP; ++w) v += s_bins[w][lan];
        if (v != 0.0f) atomicAdd(&g_add_o[lan], v);
    }
    __threadfence();                               // block's adds + pot_h stores
    unsigned old = 0;
    if (lan == 0) old = atomicAdd(&g_bar[0], 1u);
    const bool fin = __shfl_sync(0xffffffffu, old, 0) == (2u * gen + 2u) * NBLK - 1u;
    if (!fin) return;                              // 31 blocks exit here

    // ── Finisher (warp 0 of last-arriving block): totals -> outputs (+repair)
    __threadfence();                               // acquire: all adds/stores
    float ao = 0.0f;
    if (lan < OUTN) {
        ao = g_add_o[lan];
        g_add_o[lan] = 0.0f;                       // zero-on-consume for replay
    }
    const bool out_phase = (mt >= 2);              // outputs fire at t=1 or never
    const bool f    = (lan < OUTN) && out_phase && (ao * DECAY >= THRESH);
    const unsigned m = __ballot_sync(0xffffffffu, f | (lan >= OUTN));
    const bool all_f = out_phase && (m == 0xffffffffu);
    const float fac  = all_f ? DECAY : fac_long;   // decay^(S-1)

    if (lan < OUTN) {
        out[lan]        = f ? 1.0f : -1.0f;                   // out_t
        out[OUTN + lan] = out_phase ? ao * fac : 0.0f;        // pot_o
    }

    // Repair (not taken when all outputs fire at t=1): rescale speculative
    // pot_h from pot*DECAY to pot*fac_long.
    if (mt >= 1 && !all_f) {
        const float r = fac_long / DECAY;
        for (int i = lan; i < HID; i += 32)
            out[2 * OUTN + i] *= r;
    }
}

extern "C" void kernel_launch(void* const* d_in, const int* in_sizes, int n_in,
                              void* d_out, int out_size) {
    const float* spikes = (const float*)d_in[0];   // (40,)
    const float* w0     = (const float*)d_in[1];   // (40, 8192)
    const int*   tgt0   = (const int*)  d_in[2];   // (40, 8192)
    const float* w1     = (const float*)d_in[3];   // (16384, 11)
    const int*   tgt1   = (const int*)  d_in[4];   // (16384, 11)
    const int*   mt     = (const int*)  d_in[5];   // scalar max_timesteps
    float* out = (float*)d_out;

    snn_fused<<<NBLK, NTHR>>>(spikes, w0, tgt0, w1, tgt1, mt, out);
}

// round 9
// speedup vs baseline: 1.1572x; 1.1572x over previous
#include <cuda_runtime.h>

#define INN   40
#define HID   16384
#define OUTN  22
#define FAN0  8192
#define FAN1  11
#define THRESH 0.3f
#define NBLK  64
#define NTHR  256
#define NWARP (NTHR / 32)
#define NTOT  (NBLK * NTHR)             // 16384 threads == HID
#define DECAY 0.95122942450071400910f   // float32(exp(-1/20))

// Scratch — __device__ globals (allocation-free rule). g_add_h / g_add_o are
// zero at load and restored to zero every execution (zero-on-consume). g_bar is
// MONOTONIC (never reset): replay r uses window [2r*NBLK, 2(r+1)*NBLK); g_gen
// is the gate/replay counter on its OWN 128B line (spinner polls must not
// contend with arrival atomics at the LTS — R8 regression proved this).
__device__ float g_add_h[HID];
__device__ float g_add_o[OUTN];
__device__ __align__(128) unsigned g_bar[32];   // [0]: monotonic arrival counter
__device__ __align__(128) unsigned g_gen[32];   // [0]: gate word / replay index

__global__ __launch_bounds__(NTHR, 1)
void snn_fused(const float* __restrict__ spikes,
               const float* __restrict__ w0,
               const int*   __restrict__ tgt0,
               const float* __restrict__ w1,
               const int*   __restrict__ tgt1,
               const int*   __restrict__ mt_p,
               float*       __restrict__ out)
{
    __shared__ float s_spk[INN];          // 2 * input_spikes
    __shared__ float s_bins[NWARP][24];   // warp-private output bins (22 used)

    const int tid = threadIdx.x;
    const int gid = blockIdx.x * NTHR + tid;   // one hidden neuron per thread
    const int wrp = tid >> 5;
    const int lan = tid & 31;

    // ── Stage spikes (broadcast line) + zero bins
    if (tid < INN) s_spk[tid] = 2.0f * spikes[tid];
    if (lan < 24) s_bins[wrp][lan] = 0.0f;

    // ── Vectorized speculative prefetch of phase-B operands.
    // Flat element space [0, 40*8192). Thread owns float4 chunks at vec index
    // gid + 16384*k (k=0..4): 5 float4 + 5 int4 = 10 wide LDGs (vs 40 scalar).
    // Chunk k lies entirely in input row i0 + 8k, i0 = gid>>11 (warp-uniform).
    const float4* w0v = (const float4*)w0;
    const int4*   t0v = (const int4*)tgt0;
    float4 wv[5];
    int4   tv[5];
#pragma unroll
    for (int k = 0; k < 5; ++k) {
        wv[k] = __ldg(w0v + (gid + NTOT * k));
        tv[k] = __ldg(t0v + (gid + NTOT * k));
    }

    // ── Prefetch phase-C operands (consumed after barrier 1)
    float w1r[FAN1];
    int   t1r[FAN1];
    {
        const float* wr = w1   + gid * FAN1;
        const int*   tr = tgt1 + gid * FAN1;
#pragma unroll
        for (int q = 0; q < FAN1; ++q) { w1r[q] = __ldg(wr + q); t1r[q] = __ldg(tr + q); }
    }
    const int mt = __ldg(mt_p);
    const unsigned gen = *(volatile unsigned*)&g_gen[0];   // replay index

    // fac_long = decay^(mt-1) (hidden under phase B; finisher/repair only)
    float fac_long = 1.0f;
    for (int k = 1; k < mt; ++k) fac_long *= DECAY;

    __syncthreads();   // s_spk + bins visible

    // ── Phase B: input -> hidden scatter (t=0). Per chunk: one warp-uniform
    // spike lookup, 4 predicated REDs with operands already in registers.
    const int i0 = gid >> 11;
#pragma unroll
    for (int k = 0; k < 5; ++k) {
        const float s = s_spk[i0 + 8 * k];
        if (s != 0.0f) {
            atomicAdd(&g_add_h[tv[k].x], s * wv[k].x);
            atomicAdd(&g_add_h[tv[k].y], s * wv[k].y);
            atomicAdd(&g_add_h[tv[k].z], s * wv[k].z);
            atomicAdd(&g_add_h[tv[k].w], s * wv[k].w);
        }
    }

    // ── Barrier 1: arrivals on g_bar, gate on g_gen (separate lines).
    __syncthreads();
    if (tid == 0) {
        __threadfence();                                       // release
        unsigned old = atomicAdd(&g_bar[0], 1u);
        if (old == (2u * gen + 1u) * NBLK - 1u) {
            *(volatile unsigned*)&g_gen[0] = gen + 1u;         // open gate
        } else {
            while (*(volatile unsigned*)&g_gen[0] == gen) { }
        }
        __threadfence();                                       // acquire
    }
    __syncthreads();

    // ── Phase C: hidden threshold (spikes possible only at t=0) + out scatter
    float a = g_add_h[gid] * DECAY;               // pot_h at end of t=0
    g_add_h[gid] = 0.0f;                          // zero-on-consume for replay
    const bool  sp  = (a >= THRESH);
    const float pot = sp ? 0.0f : a;

    // Speculative pot_h store: assume all_f=true => S=2 => fac=DECAY.
    out[2 * OUTN + gid] = (mt >= 1) ? pot * DECAY : 0.0f;

    if (sp) {
#pragma unroll
        for (int q = 0; q < FAN1; ++q)
            atomicAdd(&s_bins[wrp][t1r[q]], w1r[q]);   // prefetched, no loads
    }
    __syncthreads();
    if (wrp != 0) return;                          // warps 1..7 done

    // ── Warp 0: post output partials, arrive; only the LAST block finalizes.
    float v = 0.0f;
    if (lan < OUTN) {
#pragma unroll
        for (int w = 0; w < NWARP; ++w) v += s_bins[w][lan];
        if (v != 0.0f) atomicAdd(&g_add_o[lan], v);
    }
    __threadfence();                               // block's adds + pot_h stores
    unsigned old = 0;
    if (lan == 0) old = atomicAdd(&g_bar[0], 1u);
    const bool fin = __shfl_sync(0xffffffffu, old, 0) == (2u * gen + 2u) * NBLK - 1u;
    if (!fin) return;                              // 63 blocks exit here

    // ── Finisher (warp 0 of last-arriving block): totals -> outputs (+repair)
    __threadfence();                               // acquire: all adds/stores
    float ao = 0.0f;
    if (lan < OUTN) {
        ao = g_add_o[lan];
        g_add_o[lan] = 0.0f;                       // zero-on-consume for replay
    }
    const bool out_phase = (mt >= 2);              // outputs fire at t=1 or never
    const bool f    = (lan < OUTN) && out_phase && (ao * DECAY >= THRESH);
    const unsigned m = __ballot_sync(0xffffffffu, f | (lan >= OUTN));
    const bool all_f = out_phase && (m == 0xffffffffu);
    const float fac  = all_f ? DECAY : fac_long;   // decay^(S-1)

    if (lan < OUTN) {
        out[lan]        = f ? 1.0f : -1.0f;                   // out_t
        out[OUTN + lan] = out_phase ? ao * fac : 0.0f;        // pot_o
    }

    // Repair (not taken when all outputs fire at t=1): rescale speculative
    // pot_h from pot*DECAY to pot*fac_long.
    if (mt >= 1 && !all_f) {
        const float r = fac_long / DECAY;
        for (int i = lan; i < HID; i += 32)
            out[2 * OUTN + i] *= r;
    }
}

extern "C" void kernel_launch(void* const* d_in, const int* in_sizes, int n_in,
                              void* d_out, int out_size) {
    const float* spikes = (const float*)d_in[0];   // (40,)
    const float* w0     = (const float*)d_in[1];   // (40, 8192)
    const int*   tgt0   = (const int*)  d_in[2];   // (40, 8192)
    const float* w1     = (const float*)d_in[3];   // (16384, 11)
    const int*   tgt1   = (const int*)  d_in[4];   // (16384, 11)
    const int*   mt     = (const int*)  d_in[5];   // scalar max_timesteps
    float* out = (float*)d_out;

    snn_fused<<<NBLK, NTHR>>>(spikes, w0, tgt0, w1, tgt1, mt, out);
}